// round 7
// baseline (speedup 1.0000x reference)
#include <cuda_runtime.h>
#include <math.h>

// Problem constants
#define B_     16
#define HH     28
#define WW     28
#define HW     784
#define C_ALL  3072
#define C4     2048
#define C3     1024
#define H4     14
#define HW4    196
#define NL     9
#define NK     2000

#define NCH4   16   // l4 chunks (128 ch each) over 2048, contraction at 14x14
#define NCH3   8    // l3 chunks (128 ch each) over 1024, contraction at 28x28

// Output layout: class_scores (16*2000), maps (16*9*784), all_features (16*3072*9)
#define CLS_OFF  0
#define MAPS_OFF (B_*NK)                  // 32000
#define FEAT_OFF (MAPS_OFF + B_*NL*HW)    // 144896

// Scratch (static __device__ arrays: allocation-free)
__device__ float g_asq[NL];
__device__ float g_p4[(size_t)B_*NCH4*NL*HW4];        // 1.8 MB partial ab4 [b][ch][l][q]
__device__ float g_part3[(size_t)NCH3*B_*NL*HW];      // 3.6 MB partial ab3 [ch][b][l][px]
__device__ float g_ab4[(size_t)B_*NL*HW4];            // summed ab4 (14x14)
__device__ float g_md[(size_t)B_*NL*HW4];             // adjoint-downsampled maps
__device__ float g_modavg[(size_t)C_ALL*B_];          // [c][b]

// ---------------------------------------------------------------------------
// K0: a_sq[l] = ||W_land[l]||^2  (one block per landmark)
// ---------------------------------------------------------------------------
__global__ void k_asq(const float* __restrict__ Wl) {
    int l = blockIdx.x, tid = threadIdx.x, warp = tid >> 5, lane = tid & 31;
    __shared__ float red[8];
    float s = 0.f;
    for (int i = tid; i < C_ALL; i += 256) {
        float w = Wl[l * C_ALL + i];
        s = fmaf(w, w, s);
    }
    #pragma unroll
    for (int o = 16; o; o >>= 1) s += __shfl_xor_sync(0xffffffffu, s, o);
    if (lane == 0) red[warp] = s;
    __syncthreads();
    if (tid == 0) {
        float t = 0.f;
        #pragma unroll
        for (int w = 0; w < 8; w++) t += red[w];
        g_asq[l] = t;
    }
}

// ---------------------------------------------------------------------------
// K1: fused landmark-logit contraction over 128-channel chunks.
//  chunk <  NCH4 : ab4 partials at 14x14 (direct coalesced LDG, no staging)
//  chunk >= NCH4 : ab3 partials at 28x28 (float4 per thread)
// Weights staged transposed [c][12] -> 2xLDS.128 + LDS per channel.
// ---------------------------------------------------------------------------
__global__ __launch_bounds__(196, 3) void k_ab(const float* __restrict__ l3,
                                               const float* __restrict__ l4,
                                               const float* __restrict__ Wl) {
    __shared__ float sWt[128 * 12];     // 6 KB, [c][l] padded to 12

    int b = blockIdx.y, chunk = blockIdx.x, tid = threadIdx.x;

    if (chunk < NCH4) {
        int c0 = chunk * 128;
        for (int i = tid; i < 128 * NL; i += 196) {
            int c = i / 9, l = i - c * 9;
            sWt[c * 12 + l] = Wl[l * C_ALL + c0 + c];
        }
        const float* l4b = l4 + ((size_t)b * C4 + c0) * HW4 + tid;

        float acc[NL];
        #pragma unroll
        for (int l = 0; l < NL; l++) acc[l] = 0.f;

        __syncthreads();
        #pragma unroll 4
        for (int c = 0; c < 128; c++) {
            float x = l4b[(size_t)c * HW4];        // coalesced LDG.32
            float4 wa = *(const float4*)&sWt[c * 12];
            float4 wb = *(const float4*)&sWt[c * 12 + 4];
            float  w8 = sWt[c * 12 + 8];
            acc[0] = fmaf(wa.x, x, acc[0]);
            acc[1] = fmaf(wa.y, x, acc[1]);
            acc[2] = fmaf(wa.z, x, acc[2]);
            acc[3] = fmaf(wa.w, x, acc[3]);
            acc[4] = fmaf(wb.x, x, acc[4]);
            acc[5] = fmaf(wb.y, x, acc[5]);
            acc[6] = fmaf(wb.z, x, acc[6]);
            acc[7] = fmaf(wb.w, x, acc[7]);
            acc[8] = fmaf(w8,   x, acc[8]);
        }
        float* dst = g_p4 + ((size_t)(b * NCH4 + chunk) * NL) * HW4 + tid;
        #pragma unroll
        for (int l = 0; l < NL; l++) dst[(size_t)l * HW4] = acc[l];
    } else {
        int ch3 = chunk - NCH4;
        int c0 = ch3 * 128;
        for (int i = tid; i < 128 * NL; i += 196) {
            int c = i / 9, l = i - c * 9;
            sWt[c * 12 + l] = Wl[l * C_ALL + C4 + c0 + c];
        }
        int px = tid * 4;

        float4 acc4[NL];
        #pragma unroll
        for (int l = 0; l < NL; l++) acc4[l] = make_float4(0.f, 0.f, 0.f, 0.f);

        const float* x3 = l3 + ((size_t)b * C3 + c0) * HW + px;
        __syncthreads();
        #pragma unroll 2
        for (int c = 0; c < 128; c++) {
            float4 xv = *(const float4*)(x3 + (size_t)c * HW);
            float4 wa = *(const float4*)&sWt[c * 12];
            float4 wb = *(const float4*)&sWt[c * 12 + 4];
            float  w8 = sWt[c * 12 + 8];
            float ws[NL] = {wa.x, wa.y, wa.z, wa.w, wb.x, wb.y, wb.z, wb.w, w8};
            #pragma unroll
            for (int l = 0; l < NL; l++) {
                acc4[l].x = fmaf(ws[l], xv.x, acc4[l].x);
                acc4[l].y = fmaf(ws[l], xv.y, acc4[l].y);
                acc4[l].z = fmaf(ws[l], xv.z, acc4[l].z);
                acc4[l].w = fmaf(ws[l], xv.w, acc4[l].w);
            }
        }
        // coalesced float4 stores: [ch][b][l][px]
        float* base = g_part3 + (((size_t)ch3 * B_ + b) * NL) * HW + px;
        #pragma unroll
        for (int l = 0; l < NL; l++)
            *(float4*)(base + (size_t)l * HW) = acc4[l];
    }
}

// ---------------------------------------------------------------------------
// K2: reduce ab4 partials only (ab3 reduction is fused into k_softmax)
// ---------------------------------------------------------------------------
__global__ void k_red() {
    int idx = blockIdx.x * 256 + threadIdx.x;
    if (idx >= B_ * NL * HW4) return;
    int b = idx / (NL * HW4), r = idx - b * (NL * HW4);
    const float* p = g_p4 + (size_t)b * NCH4 * NL * HW4 + r;
    float s = 0.f;
    #pragma unroll
    for (int ch = 0; ch < NCH4; ch++) s += p[(size_t)ch * NL * HW4];
    g_ab4[idx] = s;
}

// ---------------------------------------------------------------------------
// K3: upsample ab4 (9 ch), sum ab3 partials (coalesced), softmax, write maps.
// ---------------------------------------------------------------------------
__global__ void k_softmax(float* __restrict__ out) {
    int idx = blockIdx.x * blockDim.x + threadIdx.x;
    if (idx >= B_ * HW) return;
    int b = idx / HW, px = idx - b * HW;
    int py = px / WW, pxx = px - py * WW;

    float cyf = 0.5f * (float)py - 0.25f;
    int iyf = (int)floorf(cyf);
    float wy = cyf - (float)iyf;
    int iy0 = iyf < 0 ? 0 : iyf;
    int iy1 = (iyf + 1) > 13 ? 13 : (iyf + 1);
    float cxf = 0.5f * (float)pxx - 0.25f;
    int ixf = (int)floorf(cxf);
    float wx = cxf - (float)ixf;
    int ix0 = ixf < 0 ? 0 : ixf;
    int ix1 = (ixf + 1) > 13 ? 13 : (ixf + 1);
    int oa0 = iy0 * H4 + ix0, oa1 = iy0 * H4 + ix1;
    int ob0 = iy1 * H4 + ix0, ob1 = iy1 * H4 + ix1;

    float s[NL];
    const float* A = g_ab4 + (size_t)b * NL * HW4;
    #pragma unroll
    for (int l = 0; l < NL; l++) {
        const float* r = A + l * HW4;
        float a0 = r[oa0], a1 = r[oa1], b0 = r[ob0], b1 = r[ob1];
        float t = fmaf(wx, a1 - a0, a0);
        float u = fmaf(wx, b1 - b0, b0);
        s[l] = fmaf(wy, u - t, t);
    }

    // ab3 chunk reduction, fully coalesced LDG.32
    #pragma unroll
    for (int ch = 0; ch < NCH3; ch++) {
        const float* p = g_part3 + (((size_t)ch * B_ + b) * NL) * HW + px;
        #pragma unroll
        for (int l = 0; l < NL; l++) s[l] += p[(size_t)l * HW];
    }

    float lg[NL], m = -1e30f;
    #pragma unroll
    for (int l = 0; l < NL; l++) {
        lg[l] = 2.f * s[l] - g_asq[l];
        m = fmaxf(m, lg[l]);
    }
    float e[NL], den = 0.f;
    #pragma unroll
    for (int l = 0; l < NL; l++) { e[l] = __expf(lg[l] - m); den += e[l]; }
    float inv = 1.f / den;

    float* mp = out + MAPS_OFF + (size_t)b * NL * HW + px;
    #pragma unroll
    for (int l = 0; l < NL; l++) mp[(size_t)l * HW] = e[l] * inv;
}

// ---------------------------------------------------------------------------
// K4: adjoint-downsample of maps: md[b][l][q] = sum_px maps[b][l][px]*w(px,q).
// ---------------------------------------------------------------------------
__global__ void k_mapsdown(const float* __restrict__ out) {
    int idx = blockIdx.x * 256 + threadIdx.x;
    if (idx >= B_ * NL * HW4) return;
    int b = idx / (NL * HW4), r = idx - b * (NL * HW4);
    int l = r / HW4, q = r - l * HW4;
    int iy = q / H4, ix = q - iy * H4;

    const float* mp = out + MAPS_OFF + ((size_t)b * NL + l) * HW;

    float s = 0.f;
    #pragma unroll
    for (int dy = 0; dy < 4; dy++) {
        int py = 2 * iy - 1 + dy;
        if (py < 0 || py > 27) continue;
        float cy = 0.5f * (float)py - 0.25f;
        int iyf = (int)floorf(cy);
        float wy = cy - (float)iyf;
        int r0 = iyf < 0 ? 0 : iyf;
        int r1 = (iyf + 1) > 13 ? 13 : (iyf + 1);
        float wr = (r0 == iy ? 1.f - wy : 0.f) + (r1 == iy ? wy : 0.f);
        if (wr == 0.f) continue;
        #pragma unroll
        for (int dx = 0; dx < 4; dx++) {
            int pxx = 2 * ix - 1 + dx;
            if (pxx < 0 || pxx > 27) continue;
            float cx = 0.5f * (float)pxx - 0.25f;
            int ixf = (int)floorf(cx);
            float wxv = cx - (float)ixf;
            int c0 = ixf < 0 ? 0 : ixf;
            int c1 = (ixf + 1) > 13 ? 13 : (ixf + 1);
            float wc = (c0 == ix ? 1.f - wxv : 0.f) + (c1 == ix ? wxv : 0.f);
            if (wc == 0.f) continue;
            s = fmaf(wr * wc, mp[py * WW + pxx], s);
        }
    }
    g_md[idx] = s;
}

// ---------------------------------------------------------------------------
// K5: all_features (+fused modulation average). Thread owns TWO channels x 1 l.
// Block covers 64 channels: p=tid/9 (0..31) -> channels 2p,2p+1; l=tid%9.
//  cg <  32 : l4 channels, K=196 against g_md   (adjoint trick)
//  cg >= 32 : l3 channels, K=784 against maps (4 px-chunks of 196)
// ---------------------------------------------------------------------------
__global__ __launch_bounds__(288) void k_feat(const float* __restrict__ l3,
                                              const float* __restrict__ l4,
                                              const float* __restrict__ mod,
                                              float* __restrict__ out) {
    extern __shared__ float4 smem4[];
    float4* sX = smem4;               // 64 ch x 49 float4
    float4* sM = smem4 + 64 * 49;     // 9 maps x 49 float4
    float*  sF = (float*)(smem4 + 64 * 49 + NL * 49);  // 2*288 floats

    int b = blockIdx.y, cg = blockIdx.x, tid = threadIdx.x;
    int p = tid / 9, l = tid - p * 9;

    float4 a0 = make_float4(0.f, 0.f, 0.f, 0.f);
    float4 a1 = make_float4(0.f, 0.f, 0.f, 0.f);
    int cglobal;   // first of the two channels

    if (cg < 32) {
        int c0 = cg * 64;
        cglobal = c0 + 2 * p;
        const float4* md4 = (const float4*)(g_md + (size_t)b * NL * HW4);
        for (int i = tid; i < NL * 49; i += 288) sM[i] = md4[i];
        const float4* src = (const float4*)(l4 + ((size_t)b * C4 + c0) * HW4);
        for (int i = tid; i < 64 * 49; i += 288) sX[i] = src[i];
        __syncthreads();

        const float4* xr0 = sX + (2 * p) * 49;
        const float4* xr1 = xr0 + 49;
        const float4* mr  = sM + l * 49;
        #pragma unroll 7
        for (int i = 0; i < 49; i++) {
            float4 m = mr[i], x0 = xr0[i], x1 = xr1[i];
            a0.x = fmaf(x0.x, m.x, a0.x);
            a0.y = fmaf(x0.y, m.y, a0.y);
            a0.z = fmaf(x0.z, m.z, a0.z);
            a0.w = fmaf(x0.w, m.w, a0.w);
            a1.x = fmaf(x1.x, m.x, a1.x);
            a1.y = fmaf(x1.y, m.y, a1.y);
            a1.z = fmaf(x1.z, m.z, a1.z);
            a1.w = fmaf(x1.w, m.w, a1.w);
        }
    } else {
        int c0 = (cg - 32) * 64;   // within l3
        cglobal = C4 + c0 + 2 * p;
        const float* mbase = out + MAPS_OFF + (size_t)b * NL * HW;
        const float* xbase = l3 + ((size_t)b * C3 + c0) * HW;

        for (int pc = 0; pc < 4; pc++) {
            for (int i = tid; i < NL * 49; i += 288) {
                int ll = i / 49, j = i - ll * 49;
                sM[i] = ((const float4*)(mbase + (size_t)ll * HW + pc * HW4))[j];
            }
            for (int i = tid; i < 64 * 49; i += 288) {
                int cc = i / 49, j = i - cc * 49;
                sX[i] = ((const float4*)(xbase + (size_t)cc * HW + pc * HW4))[j];
            }
            __syncthreads();
            const float4* xr0 = sX + (2 * p) * 49;
            const float4* xr1 = xr0 + 49;
            const float4* mr  = sM + l * 49;
            #pragma unroll 7
            for (int i = 0; i < 49; i++) {
                float4 m = mr[i], x0 = xr0[i], x1 = xr1[i];
                a0.x = fmaf(x0.x, m.x, a0.x);
                a0.y = fmaf(x0.y, m.y, a0.y);
                a0.z = fmaf(x0.z, m.z, a0.z);
                a0.w = fmaf(x0.w, m.w, a0.w);
                a1.x = fmaf(x1.x, m.x, a1.x);
                a1.y = fmaf(x1.y, m.y, a1.y);
                a1.z = fmaf(x1.z, m.z, a1.z);
                a1.w = fmaf(x1.w, m.w, a1.w);
            }
            __syncthreads();
        }
    }

    float res0 = ((a0.x + a0.y) + (a0.z + a0.w)) * (1.0f / (float)HW);
    float res1 = ((a1.x + a1.y) + (a1.z + a1.w)) * (1.0f / (float)HW);
    float* fo = out + FEAT_OFF + ((size_t)b * C_ALL + cglobal) * NL + l;
    fo[0]  = res0;
    fo[NL] = res1;

    // fused modulation average
    sF[tid]       = res0 * mod[cglobal * NL + l];
    sF[288 + tid] = res1 * mod[(cglobal + 1) * NL + l];
    __syncthreads();
    if (l == 0) {
        float s0 = 0.f, s1 = 0.f;
        #pragma unroll
        for (int l2 = 0; l2 < 8; l2++) { s0 += sF[tid + l2]; s1 += sF[288 + tid + l2]; }
        g_modavg[(size_t)cglobal * B_ + b]       = s0 * 0.125f;
        g_modavg[(size_t)(cglobal + 1) * B_ + b] = s1 * 0.125f;
    }
}

// ---------------------------------------------------------------------------
// K6: class_scores[b,k] = sum_c W_class[k,c] * mod_avg[c][b]
// ---------------------------------------------------------------------------
__global__ __launch_bounds__(256) void k_cls(const float* __restrict__ Wc,
                                             float* __restrict__ out) {
    int k = blockIdx.x, tid = threadIdx.x, warp = tid >> 5, lane = tid & 31;
    const float* wr = Wc + (size_t)k * C_ALL;

    float acc[B_];
    #pragma unroll
    for (int b = 0; b < B_; b++) acc[b] = 0.f;

    for (int c = tid; c < C_ALL; c += 256) {
        float w = wr[c];
        const float4* mv = (const float4*)(g_modavg + (size_t)c * B_);
        #pragma unroll
        for (int q = 0; q < 4; q++) {
            float4 m = mv[q];
            acc[4 * q + 0] = fmaf(w, m.x, acc[4 * q + 0]);
            acc[4 * q + 1] = fmaf(w, m.y, acc[4 * q + 1]);
            acc[4 * q + 2] = fmaf(w, m.z, acc[4 * q + 2]);
            acc[4 * q + 3] = fmaf(w, m.w, acc[4 * q + 3]);
        }
    }

    __shared__ float red[8][B_];
    #pragma unroll
    for (int b = 0; b < B_; b++) {
        float v = acc[b];
        #pragma unroll
        for (int o = 16; o; o >>= 1) v += __shfl_xor_sync(0xffffffffu, v, o);
        acc[b] = v;
    }
    if (lane == 0)
        #pragma unroll
        for (int b = 0; b < B_; b++) red[warp][b] = acc[b];
    __syncthreads();
    if (tid < B_) {
        float s = 0.f;
        #pragma unroll
        for (int w = 0; w < 8; w++) s += red[w][tid];
        out[(size_t)tid * NK + k] = s;
    }
}

// ---------------------------------------------------------------------------
extern "C" void kernel_launch(void* const* d_in, const int* in_sizes, int n_in,
                              void* d_out, int out_size) {
    const float* l3  = (const float*)d_in[0];
    const float* l4  = (const float*)d_in[1];
    const float* Wl  = (const float*)d_in[2];
    const float* Wc  = (const float*)d_in[3];
    const float* mod = (const float*)d_in[4];
    float* out = (float*)d_out;

    k_asq<<<NL, 256>>>(Wl);
    k_ab<<<dim3(NCH4 + NCH3, B_), 196>>>(l3, l4, Wl);
    k_red<<<(B_ * NL * HW4 + 255) / 256, 256>>>();
    k_softmax<<<(B_ * HW + 255) / 256, 256>>>(out);
    k_mapsdown<<<(B_ * NL * HW4 + 255) / 256, 256>>>(out);

    size_t smf = (size_t)(64 * 49 + NL * 49) * sizeof(float4) + 2 * 288 * sizeof(float);
    cudaFuncSetAttribute(k_feat, cudaFuncAttributeMaxDynamicSharedMemorySize, (int)smf);
    k_feat<<<dim3(48, B_), 288, smf>>>(l3, l4, mod, out);

    k_cls<<<NK, 256>>>(Wc, out);
}

// round 8
// speedup vs baseline: 1.1722x; 1.1722x over previous
#include <cuda_runtime.h>
#include <math.h>

// Problem constants
#define B_     16
#define HH     28
#define WW     28
#define HW     784
#define C_ALL  3072
#define C4     2048
#define C3     1024
#define H4     14
#define HW4    196
#define NL     9
#define NK     2000

#define NCH4   32   // l4 chunks (64 ch each) over 2048, contraction at 14x14
#define NCH3   16   // l3 chunks (64 ch each) over 1024, contraction at 28x28

// Output layout: class_scores (16*2000), maps (16*9*784), all_features (16*3072*9)
#define CLS_OFF  0
#define MAPS_OFF (B_*NK)                  // 32000
#define FEAT_OFF (MAPS_OFF + B_*NL*HW)    // 144896

// Scratch (static __device__ arrays: allocation-free)
__device__ float g_asq[NL];
__device__ float g_p4[(size_t)B_*NCH4*NL*HW4];        // 3.6 MB partial ab4 [b][ch][l][q]
__device__ float g_part3[(size_t)NCH3*B_*NL*HW];      // 7.1 MB partial ab3 [ch][b][l][px]
__device__ float g_ab4[(size_t)B_*NL*HW4];            // summed ab4 (14x14)
__device__ float g_md[(size_t)B_*NL*HW4];             // adjoint-downsampled maps
__device__ float g_modavg[(size_t)C_ALL*B_];          // [c][b]

// ---------------------------------------------------------------------------
// K0: a_sq[l] = ||W_land[l]||^2  (one block per landmark)
// ---------------------------------------------------------------------------
__global__ void k_asq(const float* __restrict__ Wl) {
    int l = blockIdx.x, tid = threadIdx.x, warp = tid >> 5, lane = tid & 31;
    __shared__ float red[8];
    float s = 0.f;
    for (int i = tid; i < C_ALL; i += 256) {
        float w = Wl[l * C_ALL + i];
        s = fmaf(w, w, s);
    }
    #pragma unroll
    for (int o = 16; o; o >>= 1) s += __shfl_xor_sync(0xffffffffu, s, o);
    if (lane == 0) red[warp] = s;
    __syncthreads();
    if (tid == 0) {
        float t = 0.f;
        #pragma unroll
        for (int w = 0; w < 8; w++) t += red[w];
        g_asq[l] = t;
    }
}

// ---------------------------------------------------------------------------
// K1: fused landmark-logit contraction over 64-channel chunks (768 blocks).
//  chunk <  NCH4 : ab4 partials at 14x14 (direct coalesced LDG, no staging)
//  chunk >= NCH4 : ab3 partials at 28x28 (float4 per thread)
// Weights staged transposed [c][12] -> 2xLDS.128 + LDS per channel.
// ---------------------------------------------------------------------------
__global__ __launch_bounds__(196) void k_ab(const float* __restrict__ l3,
                                            const float* __restrict__ l4,
                                            const float* __restrict__ Wl) {
    __shared__ float sWt[64 * 12];      // 3 KB, [c][l] padded to 12

    int b = blockIdx.y, chunk = blockIdx.x, tid = threadIdx.x;

    if (chunk < NCH4) {
        int c0 = chunk * 64;
        for (int i = tid; i < 64 * NL; i += 196) {
            int c = i / 9, l = i - c * 9;
            sWt[c * 12 + l] = Wl[l * C_ALL + c0 + c];
        }
        const float* l4b = l4 + ((size_t)b * C4 + c0) * HW4 + tid;

        float acc[NL];
        #pragma unroll
        for (int l = 0; l < NL; l++) acc[l] = 0.f;

        __syncthreads();
        #pragma unroll 8
        for (int c = 0; c < 64; c++) {
            float x = l4b[(size_t)c * HW4];        // coalesced LDG.32
            float4 wa = *(const float4*)&sWt[c * 12];
            float4 wb = *(const float4*)&sWt[c * 12 + 4];
            float  w8 = sWt[c * 12 + 8];
            acc[0] = fmaf(wa.x, x, acc[0]);
            acc[1] = fmaf(wa.y, x, acc[1]);
            acc[2] = fmaf(wa.z, x, acc[2]);
            acc[3] = fmaf(wa.w, x, acc[3]);
            acc[4] = fmaf(wb.x, x, acc[4]);
            acc[5] = fmaf(wb.y, x, acc[5]);
            acc[6] = fmaf(wb.z, x, acc[6]);
            acc[7] = fmaf(wb.w, x, acc[7]);
            acc[8] = fmaf(w8,   x, acc[8]);
        }
        float* dst = g_p4 + ((size_t)(b * NCH4 + chunk) * NL) * HW4 + tid;
        #pragma unroll
        for (int l = 0; l < NL; l++) dst[(size_t)l * HW4] = acc[l];
    } else {
        int ch3 = chunk - NCH4;
        int c0 = ch3 * 64;
        for (int i = tid; i < 64 * NL; i += 196) {
            int c = i / 9, l = i - c * 9;
            sWt[c * 12 + l] = Wl[l * C_ALL + C4 + c0 + c];
        }
        int px = tid * 4;

        float4 acc4[NL];
        #pragma unroll
        for (int l = 0; l < NL; l++) acc4[l] = make_float4(0.f, 0.f, 0.f, 0.f);

        const float* x3 = l3 + ((size_t)b * C3 + c0) * HW + px;
        __syncthreads();
        #pragma unroll 4
        for (int c = 0; c < 64; c++) {
            float4 xv = *(const float4*)(x3 + (size_t)c * HW);
            float4 wa = *(const float4*)&sWt[c * 12];
            float4 wb = *(const float4*)&sWt[c * 12 + 4];
            float  w8 = sWt[c * 12 + 8];
            float ws[NL] = {wa.x, wa.y, wa.z, wa.w, wb.x, wb.y, wb.z, wb.w, w8};
            #pragma unroll
            for (int l = 0; l < NL; l++) {
                acc4[l].x = fmaf(ws[l], xv.x, acc4[l].x);
                acc4[l].y = fmaf(ws[l], xv.y, acc4[l].y);
                acc4[l].z = fmaf(ws[l], xv.z, acc4[l].z);
                acc4[l].w = fmaf(ws[l], xv.w, acc4[l].w);
            }
        }
        // coalesced float4 stores: [ch][b][l][px]
        float* base = g_part3 + (((size_t)ch3 * B_ + b) * NL) * HW + px;
        #pragma unroll
        for (int l = 0; l < NL; l++)
            *(float4*)(base + (size_t)l * HW) = acc4[l];
    }
}

// ---------------------------------------------------------------------------
// K2: reduce ab4 partials (ab3 reduction is fused into k_softmax)
// ---------------------------------------------------------------------------
__global__ void k_red() {
    int idx = blockIdx.x * 64 + threadIdx.x;
    if (idx >= B_ * NL * HW4) return;
    int b = idx / (NL * HW4), r = idx - b * (NL * HW4);
    const float* p = g_p4 + (size_t)b * NCH4 * NL * HW4 + r;
    float s = 0.f;
    #pragma unroll
    for (int ch = 0; ch < NCH4; ch++) s += p[(size_t)ch * NL * HW4];
    g_ab4[idx] = s;
}

// ---------------------------------------------------------------------------
// K3: upsample ab4 (9 ch), sum ab3 partials (coalesced), softmax, write maps.
// 64-thread blocks -> 196 blocks spread over the chip.
// ---------------------------------------------------------------------------
__global__ __launch_bounds__(64) void k_softmax(float* __restrict__ out) {
    int idx = blockIdx.x * 64 + threadIdx.x;
    if (idx >= B_ * HW) return;
    int b = idx / HW, px = idx - b * HW;
    int py = px / WW, pxx = px - py * WW;

    float cyf = 0.5f * (float)py - 0.25f;
    int iyf = (int)floorf(cyf);
    float wy = cyf - (float)iyf;
    int iy0 = iyf < 0 ? 0 : iyf;
    int iy1 = (iyf + 1) > 13 ? 13 : (iyf + 1);
    float cxf = 0.5f * (float)pxx - 0.25f;
    int ixf = (int)floorf(cxf);
    float wx = cxf - (float)ixf;
    int ix0 = ixf < 0 ? 0 : ixf;
    int ix1 = (ixf + 1) > 13 ? 13 : (ixf + 1);
    int oa0 = iy0 * H4 + ix0, oa1 = iy0 * H4 + ix1;
    int ob0 = iy1 * H4 + ix0, ob1 = iy1 * H4 + ix1;

    float s[NL];
    const float* A = g_ab4 + (size_t)b * NL * HW4;
    #pragma unroll
    for (int l = 0; l < NL; l++) {
        const float* r = A + l * HW4;
        float a0 = r[oa0], a1 = r[oa1], b0 = r[ob0], b1 = r[ob1];
        float t = fmaf(wx, a1 - a0, a0);
        float u = fmaf(wx, b1 - b0, b0);
        s[l] = fmaf(wy, u - t, t);
    }

    // ab3 chunk reduction, fully coalesced LDG.32
    #pragma unroll
    for (int ch = 0; ch < NCH3; ch++) {
        const float* p = g_part3 + (((size_t)ch * B_ + b) * NL) * HW + px;
        #pragma unroll
        for (int l = 0; l < NL; l++) s[l] += p[(size_t)l * HW];
    }

    float lg[NL], m = -1e30f;
    #pragma unroll
    for (int l = 0; l < NL; l++) {
        lg[l] = 2.f * s[l] - g_asq[l];
        m = fmaxf(m, lg[l]);
    }
    float e[NL], den = 0.f;
    #pragma unroll
    for (int l = 0; l < NL; l++) { e[l] = __expf(lg[l] - m); den += e[l]; }
    float inv = 1.f / den;

    float* mp = out + MAPS_OFF + (size_t)b * NL * HW + px;
    #pragma unroll
    for (int l = 0; l < NL; l++) mp[(size_t)l * HW] = e[l] * inv;
}

// ---------------------------------------------------------------------------
// K4: adjoint-downsample of maps: md[b][l][q] = sum_px maps[b][l][px]*w(px,q).
// ---------------------------------------------------------------------------
__global__ __launch_bounds__(64) void k_mapsdown(const float* __restrict__ out) {
    int idx = blockIdx.x * 64 + threadIdx.x;
    if (idx >= B_ * NL * HW4) return;
    int b = idx / (NL * HW4), r = idx - b * (NL * HW4);
    int l = r / HW4, q = r - l * HW4;
    int iy = q / H4, ix = q - iy * H4;

    const float* mp = out + MAPS_OFF + ((size_t)b * NL + l) * HW;

    float s = 0.f;
    #pragma unroll
    for (int dy = 0; dy < 4; dy++) {
        int py = 2 * iy - 1 + dy;
        if (py < 0 || py > 27) continue;
        float cy = 0.5f * (float)py - 0.25f;
        int iyf = (int)floorf(cy);
        float wy = cy - (float)iyf;
        int r0 = iyf < 0 ? 0 : iyf;
        int r1 = (iyf + 1) > 13 ? 13 : (iyf + 1);
        float wr = (r0 == iy ? 1.f - wy : 0.f) + (r1 == iy ? wy : 0.f);
        if (wr == 0.f) continue;
        #pragma unroll
        for (int dx = 0; dx < 4; dx++) {
            int pxx = 2 * ix - 1 + dx;
            if (pxx < 0 || pxx > 27) continue;
            float cx = 0.5f * (float)pxx - 0.25f;
            int ixf = (int)floorf(cx);
            float wxv = cx - (float)ixf;
            int c0 = ixf < 0 ? 0 : ixf;
            int c1 = (ixf + 1) > 13 ? 13 : (ixf + 1);
            float wc = (c0 == ix ? 1.f - wxv : 0.f) + (c1 == ix ? wxv : 0.f);
            if (wc == 0.f) continue;
            s = fmaf(wr * wc, mp[py * WW + pxx], s);
        }
    }
    g_md[idx] = s;
}

// ---------------------------------------------------------------------------
// K5: all_features (+fused modulation average).
// Thread = one channel, owns all 9 landmark accumulators.
//   x streamed directly from global (own contiguous row, L1-friendly),
//   maps/md broadcast from SMEM (uniform address per warp -> conflict-free).
//  cg <  16 : l4 channels (128/block), K=196 against g_md (adjoint trick)
//  cg >= 16 : l3 channels (128/block), K=784 against maps
// No barriers in hot loop, no reductions, modavg computed in registers.
// ---------------------------------------------------------------------------
__global__ __launch_bounds__(128) void k_feat(const float* __restrict__ l3,
                                              const float* __restrict__ l4,
                                              const float* __restrict__ mod,
                                              float* __restrict__ out) {
    __shared__ float4 sM[NL * 196];   // up to 9 x 784 floats (28.2 KB)

    int b = blockIdx.y, cg = blockIdx.x, tid = threadIdx.x;

    float acc[NL];
    #pragma unroll
    for (int l = 0; l < NL; l++) acc[l] = 0.f;

    int cglobal;

    if (cg < 16) {
        int c = cg * 128 + tid;
        cglobal = c;
        const float4* md4 = (const float4*)(g_md + (size_t)b * NL * HW4);
        for (int i = tid; i < NL * 49; i += 128) sM[i] = md4[i];
        __syncthreads();

        const float4* xr = (const float4*)(l4 + ((size_t)b * C4 + c) * HW4);
        #pragma unroll 7
        for (int i = 0; i < 49; i++) {
            float4 x = xr[i];
            #pragma unroll
            for (int l = 0; l < NL; l++) {
                float4 m = sM[l * 49 + i];
                acc[l] = fmaf(x.x, m.x, acc[l]);
                acc[l] = fmaf(x.y, m.y, acc[l]);
                acc[l] = fmaf(x.z, m.z, acc[l]);
                acc[l] = fmaf(x.w, m.w, acc[l]);
            }
        }
    } else {
        int c = (cg - 16) * 128 + tid;   // within l3
        cglobal = C4 + c;
        const float4* mp4 = (const float4*)(out + MAPS_OFF + (size_t)b * NL * HW);
        for (int i = tid; i < NL * 196; i += 128) sM[i] = mp4[i];
        __syncthreads();

        const float4* xr = (const float4*)(l3 + ((size_t)b * C3 + c) * HW);
        #pragma unroll 4
        for (int i = 0; i < 196; i++) {
            float4 x = xr[i];
            #pragma unroll
            for (int l = 0; l < NL; l++) {
                float4 m = sM[l * 196 + i];
                acc[l] = fmaf(x.x, m.x, acc[l]);
                acc[l] = fmaf(x.y, m.y, acc[l]);
                acc[l] = fmaf(x.z, m.z, acc[l]);
                acc[l] = fmaf(x.w, m.w, acc[l]);
            }
        }
    }

    const float sc = 1.0f / (float)HW;
    float* fo = out + FEAT_OFF + ((size_t)b * C_ALL + cglobal) * NL;
    float mv = 0.f;
    #pragma unroll
    for (int l = 0; l < NL; l++) {
        float r = acc[l] * sc;
        fo[l] = r;
        if (l < 8) mv = fmaf(r, mod[cglobal * NL + l], mv);
    }
    g_modavg[(size_t)cglobal * B_ + b] = mv * 0.125f;
}

// ---------------------------------------------------------------------------
// K6: class_scores[b,k] = sum_c W_class[k,c] * mod_avg[c][b]
// ---------------------------------------------------------------------------
__global__ __launch_bounds__(256) void k_cls(const float* __restrict__ Wc,
                                             float* __restrict__ out) {
    int k = blockIdx.x, tid = threadIdx.x, warp = tid >> 5, lane = tid & 31;
    const float* wr = Wc + (size_t)k * C_ALL;

    float acc[B_];
    #pragma unroll
    for (int b = 0; b < B_; b++) acc[b] = 0.f;

    for (int c = tid; c < C_ALL; c += 256) {
        float w = wr[c];
        const float4* mv = (const float4*)(g_modavg + (size_t)c * B_);
        #pragma unroll
        for (int q = 0; q < 4; q++) {
            float4 m = mv[q];
            acc[4 * q + 0] = fmaf(w, m.x, acc[4 * q + 0]);
            acc[4 * q + 1] = fmaf(w, m.y, acc[4 * q + 1]);
            acc[4 * q + 2] = fmaf(w, m.z, acc[4 * q + 2]);
            acc[4 * q + 3] = fmaf(w, m.w, acc[4 * q + 3]);
        }
    }

    __shared__ float red[8][B_];
    #pragma unroll
    for (int b = 0; b < B_; b++) {
        float v = acc[b];
        #pragma unroll
        for (int o = 16; o; o >>= 1) v += __shfl_xor_sync(0xffffffffu, v, o);
        acc[b] = v;
    }
    if (lane == 0)
        #pragma unroll
        for (int b = 0; b < B_; b++) red[warp][b] = acc[b];
    __syncthreads();
    if (tid < B_) {
        float s = 0.f;
        #pragma unroll
        for (int w = 0; w < 8; w++) s += red[w][tid];
        out[(size_t)tid * NK + k] = s;
    }
}

// ---------------------------------------------------------------------------
extern "C" void kernel_launch(void* const* d_in, const int* in_sizes, int n_in,
                              void* d_out, int out_size) {
    const float* l3  = (const float*)d_in[0];
    const float* l4  = (const float*)d_in[1];
    const float* Wl  = (const float*)d_in[2];
    const float* Wc  = (const float*)d_in[3];
    const float* mod = (const float*)d_in[4];
    float* out = (float*)d_out;

    k_asq<<<NL, 256>>>(Wl);
    k_ab<<<dim3(NCH4 + NCH3, B_), 196>>>(l3, l4, Wl);
    k_red<<<(B_ * NL * HW4 + 63) / 64, 64>>>();
    k_softmax<<<(B_ * HW + 63) / 64, 64>>>(out);
    k_mapsdown<<<(B_ * NL * HW4 + 63) / 64, 64>>>(out);
    k_feat<<<dim3(24, B_), 128>>>(l3, l4, mod, out);
    k_cls<<<NK, 256>>>(Wc, out);
}